// round 9
// baseline (speedup 1.0000x reference)
#include <cuda_runtime.h>
#include <cuda_bf16.h>
#include <math_constants.h>

#define THREADS 256
#define D 4096
#define V4T (D / 4 / THREADS)   // 4 float4 per thread
#define EPT (V4T * 4)           // 16 floats per thread
#define NW (THREADS / 32)       // 8 warps
#define CANDCAP 64
#define SORTN 32

__global__ __launch_bounds__(THREADS, 8)
void sparsemax_kernel(const float* __restrict__ in, float* __restrict__ out)
{
    const long long row = blockIdx.x;
    const float4* __restrict__ rin  = reinterpret_cast<const float4*>(in  + row * (long long)D);
    float4* __restrict__       rout = reinterpret_cast<float4*>      (out + row * (long long)D);

    const int t    = threadIdx.x;
    const int lane = t & 31;
    const int wid  = t >> 5;
    const unsigned FULL = 0xFFFFFFFFu;

    __shared__ float red[NW];
    __shared__ float redb[NW];
    __shared__ float cand[CANDCAP];
    __shared__ int   s_cnt;
    __shared__ float s_tau;
    __shared__ int   s_done;

    if (t == 0) s_cnt = 0;

    // ---- Load 16 elements/thread (4x LDG.128 .cs), track thread max
    float z[EPT];
    float tm;
#pragma unroll
    for (int i = 0; i < V4T; ++i) {
        float4 v = __ldcs(rin + t + i * THREADS);
        z[4*i+0] = v.x; z[4*i+1] = v.y; z[4*i+2] = v.z; z[4*i+3] = v.w;
        float q = fmaxf(fmaxf(v.x, v.y), fmaxf(v.z, v.w));
        tm = (i == 0) ? q : fmaxf(tm, q);
    }

    // ---- Warp max -> block max
    float m = tm;
#pragma unroll
    for (int off = 16; off >= 1; off >>= 1)
        m = fmaxf(m, __shfl_xor_sync(FULL, m, off));
    if (lane == 0) red[wid] = m;
    __syncthreads();                       // B0: maxes + s_cnt=0 visible

    float zmax = red[0];
#pragma unroll
    for (int w = 1; w < NW; ++w) zmax = fmaxf(zmax, red[w]);
    const float lo = zmax - 1.0f;          // tau in [lo, zmax): only z > lo matter

    // ---- Compaction with thread-level skip: ~0.3% of threads scan their 16
    if (tm > lo) {
#pragma unroll
        for (int i = 0; i < EPT; ++i) {
            if (z[i] > lo) {
                int pos = atomicAdd(&s_cnt, 1);
                if (pos < CANDCAP) cand[pos] = z[i];
            }
        }
    }
    __syncthreads();                       // B1: candidates visible
    const int cnt = s_cnt;

    float tau;
    if (cnt <= SORTN) {
        // ---- Exact all-pairs solve, redundantly in EVERY warp.
        // For lane j: K = #{v_i >= v_j}, S = sum{v_i >= v_j}. v_j has rank K,
        // so support condition (1 + rank*v > cumsum) is 1 + K*v > S.
        // tau = (S-1)/K at the satisfying lane with max K. Ties are exact
        // (duplicates share identical K,S). 31 shfls depend only on v -> pipelined.
        const bool act = (lane < cnt);
        float v = act ? cand[lane] : -CUDART_INF_F;
        float S = act ? v    : 0.0f;
        float K = act ? 1.0f : 0.0f;
#pragma unroll
        for (int off = 1; off < 32; ++off) {
            float w = __shfl_sync(FULL, v, (lane + off) & 31);
            if (w >= v) { S += w; K += 1.0f; }
        }
        bool cond = act && (fmaf(K, v, 1.0f) > S);
        int enc = cond ? (((int)K << 5) | lane) : -1;   // argmax K, lane as tiebreak
#pragma unroll
        for (int off = 16; off >= 1; off >>= 1)
            enc = max(enc, __shfl_xor_sync(FULL, enc, off));
        int bl = enc & 31;                               // enc >= 0: zmax lane always satisfies
        float Sk = __shfl_sync(FULL, S, bl);
        float Kk = __shfl_sync(FULL, K, bl);
        tau = (Sk - 1.0f) / Kk;
    } else {
        // ---- Fallback for arbitrary data: block-wide Newton over registers
        if (t == 0) s_tau = lo;
        __syncthreads();
        float tloc = s_tau;
        for (int it = 0; it < 48; ++it) {
            float s = 0.0f, k = 0.0f;
#pragma unroll
            for (int i = 0; i < EPT; ++i) {
                float d = z[i] - tloc;
                if (d > 0.0f) { s += d; k += 1.0f; }
            }
#pragma unroll
            for (int off = 16; off >= 1; off >>= 1) {
                s += __shfl_xor_sync(FULL, s, off);
                k += __shfl_xor_sync(FULL, k, off);
            }
            if (lane == 0) { red[wid] = s; redb[wid] = k; }
            __syncthreads();
            if (t == 0) {
                float S = 0.0f, Kt = 0.0f;
#pragma unroll
                for (int w = 0; w < NW; ++w) { S += red[w]; Kt += redb[w]; }
                float delta = (S - 1.0f) / Kt;
                s_tau  = tloc + delta;
                s_done = (delta < 1e-7f);
            }
            __syncthreads();
            tloc = s_tau;
            if (s_done) break;
        }
        tau = s_tau;
    }

    // ---- Epilogue: out = max(z - tau, 0), streaming stores
#pragma unroll
    for (int i = 0; i < V4T; ++i) {
        float4 o;
        o.x = fmaxf(z[4*i+0] - tau, 0.0f);
        o.y = fmaxf(z[4*i+1] - tau, 0.0f);
        o.z = fmaxf(z[4*i+2] - tau, 0.0f);
        o.w = fmaxf(z[4*i+3] - tau, 0.0f);
        __stcs(rout + t + i * THREADS, o);
    }
}

extern "C" void kernel_launch(void* const* d_in, const int* in_sizes, int n_in,
                              void* d_out, int out_size)
{
    const float* in  = (const float*)d_in[0];
    float*       out = (float*)d_out;
    const int n_rows = in_sizes[0] / D;   // 16384
    sparsemax_kernel<<<n_rows, THREADS>>>(in, out);
}

// round 10
// speedup vs baseline: 1.6603x; 1.6603x over previous
#include <cuda_runtime.h>
#include <cuda_bf16.h>
#include <math_constants.h>

#define THREADS 256
#define D 4096
#define V4T (D / 4 / THREADS)   // 4 float4 per thread
#define EPT (V4T * 4)           // 16 floats per thread
#define NW (THREADS / 32)       // 8 warps
#define CANDCAP 64
#define SORTN 32

__global__ __launch_bounds__(THREADS, 8)
void sparsemax_kernel(const float* __restrict__ in, float* __restrict__ out)
{
    const long long row = blockIdx.x;
    const float4* __restrict__ rin  = reinterpret_cast<const float4*>(in  + row * (long long)D);
    float4* __restrict__       rout = reinterpret_cast<float4*>      (out + row * (long long)D);

    const int t    = threadIdx.x;
    const int lane = t & 31;
    const int wid  = t >> 5;
    const unsigned FULL = 0xFFFFFFFFu;

    __shared__ float red[NW];
    __shared__ float redb[NW];
    __shared__ float cand[CANDCAP];
    __shared__ int   s_cnt;
    __shared__ float s_tau;
    __shared__ int   s_done;

    if (t == 0) s_cnt = 0;

    // ---- Load 16 elements/thread (4x LDG.128 .cs), track thread max
    float z[EPT];
    float tm;
#pragma unroll
    for (int i = 0; i < V4T; ++i) {
        float4 v = __ldcs(rin + t + i * THREADS);
        z[4*i+0] = v.x; z[4*i+1] = v.y; z[4*i+2] = v.z; z[4*i+3] = v.w;
        float q = fmaxf(fmaxf(v.x, v.y), fmaxf(v.z, v.w));
        tm = (i == 0) ? q : fmaxf(tm, q);
    }

    // ---- Warp max -> smem
    float m = tm;
#pragma unroll
    for (int off = 16; off >= 1; off >>= 1)
        m = fmaxf(m, __shfl_xor_sync(FULL, m, off));
    if (lane == 0) red[wid] = m;
    __syncthreads();                       // B0: maxes + s_cnt=0 visible

    // ---- Block max: lanes<8 load red[], 3-stage shfl fold, broadcast
    float zmax = (lane < NW) ? red[lane] : -CUDART_INF_F;
#pragma unroll
    for (int off = 4; off >= 1; off >>= 1)
        zmax = fmaxf(zmax, __shfl_xor_sync(FULL, zmax, off));
    zmax = __shfl_sync(FULL, zmax, 0);
    const float lo = zmax - 1.0f;          // tau in [lo, zmax): only z > lo matter

    // ---- Compaction with thread-level skip: ~0.3% of threads scan their 16
    if (tm > lo) {
#pragma unroll
        for (int i = 0; i < EPT; ++i) {
            if (z[i] > lo) {
                int pos = atomicAdd(&s_cnt, 1);
                if (pos < CANDCAP) cand[pos] = z[i];
            }
        }
    }
    __syncthreads();                       // B1: candidates visible
    const int cnt = s_cnt;

    float tau;
    if (cnt <= 16) {
        // ---- Exact solve, 16-lane network (10 sort + 4 scan stages), every warp.
        // Both half-warps run it; upper half holds -inf and never satisfies cond.
        const int l4 = lane & 15;
        float v = (lane < cnt) ? cand[lane] : -CUDART_INF_F;
#pragma unroll
        for (int k = 2; k <= 16; k <<= 1) {
#pragma unroll
            for (int j = k >> 1; j > 0; j >>= 1) {
                float w = __shfl_xor_sync(FULL, v, j);
                bool lower   = ((l4 & j) == 0);
                bool descBlk = ((l4 & k) == 0);
                v = (lower == descBlk) ? fmaxf(v, w) : fminf(v, w);
            }
        }
        float csum = v;
#pragma unroll
        for (int off = 1; off < 16; off <<= 1) {
            float u = __shfl_up_sync(FULL, csum, off, 16);   // width=16 segments
            if (l4 >= off) csum += u;
        }
        float r = (float)(l4 + 1);
        bool cond = (lane < cnt) && (1.0f + r * v > csum);
        unsigned msk = __ballot_sync(FULL, cond);            // only lanes 0..15 can set
        int kidx = 31 - __clz(msk);                          // msk != 0: top lane satisfies
        float csk = __shfl_sync(FULL, csum, kidx);
        tau = (csk - 1.0f) / (float)(kidx + 1);
    } else if (cnt <= SORTN) {
        // ---- 32-lane network (rare: 16 < cnt <= 32)
        float v = (lane < cnt) ? cand[lane] : -CUDART_INF_F;
#pragma unroll
        for (int k = 2; k <= 32; k <<= 1) {
#pragma unroll
            for (int j = k >> 1; j > 0; j >>= 1) {
                float w = __shfl_xor_sync(FULL, v, j);
                bool lower   = ((lane & j) == 0);
                bool descBlk = ((lane & k) == 0);
                v = (lower == descBlk) ? fmaxf(v, w) : fminf(v, w);
            }
        }
        float csum = v;
#pragma unroll
        for (int off = 1; off < 32; off <<= 1) {
            float u = __shfl_up_sync(FULL, csum, off);
            if (lane >= off) csum += u;
        }
        float r = (float)(lane + 1);
        bool cond = (lane < cnt) && (1.0f + r * v > csum);
        unsigned msk = __ballot_sync(FULL, cond);
        int kidx = 31 - __clz(msk);
        float csk = __shfl_sync(FULL, csum, kidx);
        tau = (csk - 1.0f) / (float)(kidx + 1);
    } else {
        // ---- Fallback for arbitrary data: block-wide Newton over registers
        if (t == 0) s_tau = lo;
        __syncthreads();
        float tloc = s_tau;
        for (int it = 0; it < 48; ++it) {
            float s = 0.0f, k = 0.0f;
#pragma unroll
            for (int i = 0; i < EPT; ++i) {
                float d = z[i] - tloc;
                if (d > 0.0f) { s += d; k += 1.0f; }
            }
#pragma unroll
            for (int off = 16; off >= 1; off >>= 1) {
                s += __shfl_xor_sync(FULL, s, off);
                k += __shfl_xor_sync(FULL, k, off);
            }
            if (lane == 0) { red[wid] = s; redb[wid] = k; }
            __syncthreads();
            if (t == 0) {
                float S = 0.0f, K = 0.0f;
#pragma unroll
                for (int w = 0; w < NW; ++w) { S += red[w]; K += redb[w]; }
                float delta = (S - 1.0f) / K;
                s_tau  = tloc + delta;
                s_done = (delta < 1e-7f);
            }
            __syncthreads();
            tloc = s_tau;
            if (s_done) break;
        }
        tau = s_tau;
    }

    // ---- Epilogue: out = max(z - tau, 0), streaming stores
#pragma unroll
    for (int i = 0; i < V4T; ++i) {
        float4 o;
        o.x = fmaxf(z[4*i+0] - tau, 0.0f);
        o.y = fmaxf(z[4*i+1] - tau, 0.0f);
        o.z = fmaxf(z[4*i+2] - tau, 0.0f);
        o.w = fmaxf(z[4*i+3] - tau, 0.0f);
        __stcs(rout + t + i * THREADS, o);
    }
}

extern "C" void kernel_launch(void* const* d_in, const int* in_sizes, int n_in,
                              void* d_out, int out_size)
{
    const float* in  = (const float*)d_in[0];
    float*       out = (float*)d_out;
    const int n_rows = in_sizes[0] / D;   // 16384
    sparsemax_kernel<<<n_rows, THREADS>>>(in, out);
}